// round 2
// baseline (speedup 1.0000x reference)
#include <cuda_runtime.h>
#include <math.h>

#define NB   32
#define NC   128
#define NPOS 4096
#define NHD  4
#define DH   32
#define HID  128
#define NTOT (NC*NPOS)            /* 524288 per-batch elements */
#define SCALE 0.17677669529663687f
#define EPS   1e-5f

// ---------------- device scratch (static: no allocs allowed) ----------------
__device__ float g_q[NB*HID*NPOS];        // softmaxed(q)*scale, [b][h*32+d][n]
__device__ float g_k[NB*HID*NPOS];        // raw k
__device__ float g_v[NB*HID*NPOS];        // raw v
__device__ float g_kstats[NB*HID*2];      // per (b,hd): rowmax, rowsumexp
__device__ float g_ctx[NB*NHD*DH*DH];     // [b][h][d][e]
__device__ float g_M[NB*HID*NC];          // [b][hd][o]
__device__ float g_part[NB*32*2];         // per (b, ntile): sum, sumsq
__device__ float g_stats[NB*2];           // per b: mu, rstd

// ============================================================================
// K1: QKV GEMM (per batch: 384 x 4096 x 128) + q-softmax over d, fused.
// Block = (n-tile of 128, batch). smem: x tile 64KB, W^T 48.5KB, stage 48KB.
// ============================================================================
#define WT_STRIDE 97   /* 97 % 32 == 1 -> conflict-free loads AND stores */

__global__ __launch_bounds__(256) void k_qkv(const float* __restrict__ x,
                                             const float* __restrict__ Wqkv) {
    extern __shared__ float sm[];
    float* xt = sm;                          // [128][128] (c, n)
    float* wt = sm + 128*128;                // [kk][lr] stride WT_STRIDE
    float* st = wt + 128*WT_STRIDE;          // [96][128] stage (q,k,v rows)
    float4* xt4 = (float4*)xt;
    float4* st4 = (float4*)st;

    const int b   = blockIdx.y;
    const int n0  = blockIdx.x * 128;
    const int tid = threadIdx.x;
    const int ty  = tid >> 4, tx = tid & 15;
    const int r0  = ty * 6;

    // load x tile: coalesced float4
    const float4* xg = (const float4*)(x + (size_t)b*NTOT + n0);
    for (int i = tid; i < 128*32; i += 256) {
        int r = i >> 5, c4 = i & 31;
        xt4[i] = xg[(size_t)r*(NPOS/4) + c4];
    }
    __syncthreads();

    for (int h = 0; h < NHD; h++) {
        // load W slice for this head, transposed: wt[kk][lr], lr = s*32+d
        for (int i = tid; i < 96*128; i += 256) {
            int kk = i & 127, lr = i >> 7;
            int s = lr >> 5, d = lr & 31;
            wt[kk*WT_STRIDE + lr] = Wqkv[(size_t)(s*128 + h*32 + d)*128 + kk];
        }
        __syncthreads();

        float acc[6][8];
        #pragma unroll
        for (int j = 0; j < 6; j++)
            #pragma unroll
            for (int i2 = 0; i2 < 8; i2++) acc[j][i2] = 0.f;

        for (int kk = 0; kk < 128; kk++) {
            float4 xa = xt4[kk*32 + tx*2];
            float4 xb = xt4[kk*32 + tx*2 + 1];
            float xv[8] = {xa.x,xa.y,xa.z,xa.w, xb.x,xb.y,xb.z,xb.w};
            #pragma unroll
            for (int j = 0; j < 6; j++) {
                float w = wt[kk*WT_STRIDE + r0 + j];
                #pragma unroll
                for (int i2 = 0; i2 < 8; i2++)
                    acc[j][i2] = fmaf(w, xv[i2], acc[j][i2]);
            }
        }

        // stage to smem
        #pragma unroll
        for (int j = 0; j < 6; j++) {
            st4[(r0+j)*32 + tx*2]     = make_float4(acc[j][0],acc[j][1],acc[j][2],acc[j][3]);
            st4[(r0+j)*32 + tx*2 + 1] = make_float4(acc[j][4],acc[j][5],acc[j][6],acc[j][7]);
        }
        __syncthreads();

        // q softmax over d (rows 0..31) per column, times SCALE
        if (tid < 128) {
            float m = st[tid];
            for (int d = 1; d < 32; d++) m = fmaxf(m, st[d*128 + tid]);
            float ssum = 0.f;
            for (int d = 0; d < 32; d++) {
                float e = expf(st[d*128 + tid] - m);
                st[d*128 + tid] = e;
                ssum += e;
            }
            float invs = SCALE / ssum;
            for (int d = 0; d < 32; d++) st[d*128 + tid] *= invs;
        }
        __syncthreads();

        // write out: rows 0-31 q (softmaxed), 32-63 k, 64-95 v
        size_t obase = (size_t)b*HID*NPOS + (size_t)(h*32)*NPOS + n0;
        for (int i = tid; i < 96*32; i += 256) {
            int r = i >> 5, c4 = i & 31;
            float* dst = (r < 32) ? g_q : (r < 64 ? g_k : g_v);
            ((float4*)(dst + obase + (size_t)(r & 31)*NPOS))[c4] = st4[i];
        }
        __syncthreads();
    }
}

// ============================================================================
// K2: per (b,hd)-row of k: max and sum(exp) over n=4096
// ============================================================================
__global__ __launch_bounds__(256) void k_kstats() {
    __shared__ float red[256];
    const int row = blockIdx.x;
    const int tid = threadIdx.x;
    const float* kr = g_k + (size_t)row * NPOS;

    float m = -1e30f;
    for (int i = tid; i < NPOS; i += 256) m = fmaxf(m, kr[i]);
    red[tid] = m; __syncthreads();
    for (int s2 = 128; s2 > 0; s2 >>= 1) {
        if (tid < s2) red[tid] = fmaxf(red[tid], red[tid+s2]);
        __syncthreads();
    }
    m = red[0]; __syncthreads();

    float ssum = 0.f;
    for (int i = tid; i < NPOS; i += 256) ssum += expf(kr[i] - m);
    red[tid] = ssum; __syncthreads();
    for (int s2 = 128; s2 > 0; s2 >>= 1) {
        if (tid < s2) red[tid] += red[tid+s2];
        __syncthreads();
    }
    if (tid == 0) { g_kstats[row*2] = m; g_kstats[row*2+1] = red[0]; }
}

// ============================================================================
// K3: context[b,h,d,e] = sum_n softmax_k[d,n] * v[e,n]   (32x32 per (b,h))
// ============================================================================
#define CH 64
__global__ __launch_bounds__(256) void k_ctx() {
    __shared__ float ks[32*CH];        // raw k chunk [d][n]
    __shared__ float kst[CH*33];       // transformed, transposed [n][d] (pad 33)
    __shared__ float vs[32*CH];        // v chunk [e][n]
    __shared__ float mx[32], inv[32];

    const int tid = threadIdx.x;
    const int h = blockIdx.x, b = blockIdx.y;
    if (tid < 32) {
        int row = b*HID + h*32 + tid;
        mx[tid]  = g_kstats[row*2];
        inv[tid] = 1.0f / g_kstats[row*2 + 1];
    }
    const int d  = tid & 31;
    const int eg = tid >> 5;          // 8 groups of 4 e-values
    float a0=0.f, a1=0.f, a2=0.f, a3=0.f;
    const size_t base = (size_t)(b*HID + h*32) * NPOS;

    for (int n0 = 0; n0 < NPOS; n0 += CH) {
        __syncthreads();
        for (int i = tid; i < 32*(CH/4); i += 256) {      // 512 float4 each
            int r = i >> 4, c4 = i & 15;
            ((float4*)ks)[i] = *(const float4*)(g_k + base + (size_t)r*NPOS + n0 + c4*4);
            ((float4*)vs)[i] = *(const float4*)(g_v + base + (size_t)r*NPOS + n0 + c4*4);
        }
        __syncthreads();
        for (int i = tid; i < 32*CH; i += 256) {
            int r = i >> 6, c = i & (CH-1);
            kst[c*33 + r] = expf(ks[i] - mx[r]) * inv[r];
        }
        __syncthreads();
        const float* v0 = vs + (eg*4 + 0)*CH;
        const float* v1 = vs + (eg*4 + 1)*CH;
        const float* v2 = vs + (eg*4 + 2)*CH;
        const float* v3 = vs + (eg*4 + 3)*CH;
        #pragma unroll 8
        for (int nn = 0; nn < CH; nn++) {
            float kv = kst[nn*33 + d];
            a0 = fmaf(kv, v0[nn], a0);
            a1 = fmaf(kv, v1[nn], a1);
            a2 = fmaf(kv, v2[nn], a2);
            a3 = fmaf(kv, v3[nn], a3);
        }
    }
    float* cp = g_ctx + ((size_t)(b*NHD + h)*DH + d)*DH + eg*4;
    cp[0]=a0; cp[1]=a1; cp[2]=a2; cp[3]=a3;
}

// ============================================================================
// K4a: M[b][hd][o] = sum_e W_out[o][h*32+e] * ctx[b][h][d][e]   (tiny GEMM)
// ============================================================================
__global__ __launch_bounds__(256) void k_m(const float* __restrict__ Wout) {
    __shared__ float csm[NHD*DH*DH];   // 4096 floats
    const int b = blockIdx.x, tid = threadIdx.x;
    for (int i = tid; i < NHD*DH*DH; i += 256) csm[i] = g_ctx[(size_t)b*NHD*DH*DH + i];
    __syncthreads();
    for (int j = 0; j < 64; j++) {
        int m  = j*256 + tid;          // m = hd*128 + o
        int hd = m >> 7, o = m & 127;
        int hh = hd >> 5;
        const float* wrow = Wout + (size_t)o*HID + hh*32;
        const float* crow = csm + hd*32;
        float s = 0.f;
        #pragma unroll
        for (int e = 0; e < 32; e++) s = fmaf(wrow[e], crow[e], s);
        g_M[(size_t)b*HID*NC + m] = s;
    }
}

// ============================================================================
// K4b: y[b][o][n] = sum_hd M[b][hd][o]*q[b][hd][n] + b_out[o]; writes d_out,
//      per-(b,tile) partial sum/sumsq for GroupNorm.
// ============================================================================
__global__ __launch_bounds__(256) void k_y(const float* __restrict__ bout,
                                           float* __restrict__ out) {
    extern __shared__ float sm[];
    float* qt = sm;              // [hd][128]
    float* mt = sm + 128*128;    // [hd][o]  (already transposed in g_M)
    __shared__ float red[256];

    const int b = blockIdx.y, n0 = blockIdx.x*128, tid = threadIdx.x;
    const int ty = tid >> 4, tx = tid & 15;

    const float4* qg = (const float4*)(g_q + (size_t)b*HID*NPOS + n0);
    for (int i = tid; i < 128*32; i += 256) {
        int r = i >> 5, c4 = i & 31;
        ((float4*)qt)[i] = qg[(size_t)r*(NPOS/4) + c4];
    }
    const float4* mg = (const float4*)(g_M + (size_t)b*HID*NC);
    for (int i = tid; i < 128*32; i += 256) ((float4*)mt)[i] = mg[i];
    __syncthreads();

    float acc[8][8];
    #pragma unroll
    for (int j = 0; j < 8; j++)
        #pragma unroll
        for (int i2 = 0; i2 < 8; i2++) acc[j][i2] = 0.f;

    for (int kk = 0; kk < 128; kk++) {
        float4 ma = ((float4*)mt)[kk*32 + ty*2];
        float4 mb = ((float4*)mt)[kk*32 + ty*2 + 1];
        float4 qa = ((float4*)qt)[kk*32 + tx*2];
        float4 qb = ((float4*)qt)[kk*32 + tx*2 + 1];
        float av[8] = {ma.x,ma.y,ma.z,ma.w, mb.x,mb.y,mb.z,mb.w};
        float bv[8] = {qa.x,qa.y,qa.z,qa.w, qb.x,qb.y,qb.z,qb.w};
        #pragma unroll
        for (int j = 0; j < 8; j++)
            #pragma unroll
            for (int i2 = 0; i2 < 8; i2++)
                acc[j][i2] = fmaf(av[j], bv[i2], acc[j][i2]);
    }

    float lsum = 0.f, lsq = 0.f;
    #pragma unroll
    for (int j = 0; j < 8; j++) {
        int o = ty*8 + j;
        float bias = bout[o];
        #pragma unroll
        for (int i2 = 0; i2 < 8; i2++) {
            float v = acc[j][i2] + bias;
            acc[j][i2] = v;
            lsum += v;
            lsq  = fmaf(v, v, lsq);
        }
        float4* orow = (float4*)(out + (size_t)b*NTOT + (size_t)o*NPOS + n0);
        orow[tx*2]     = make_float4(acc[j][0],acc[j][1],acc[j][2],acc[j][3]);
        orow[tx*2 + 1] = make_float4(acc[j][4],acc[j][5],acc[j][6],acc[j][7]);
    }

    red[tid] = lsum; __syncthreads();
    for (int s2 = 128; s2 > 0; s2 >>= 1) {
        if (tid < s2) red[tid] += red[tid+s2];
        __syncthreads();
    }
    if (tid == 0) g_part[(b*32 + blockIdx.x)*2] = red[0];
    __syncthreads();
    red[tid] = lsq; __syncthreads();
    for (int s2 = 128; s2 > 0; s2 >>= 1) {
        if (tid < s2) red[tid] += red[tid+s2];
        __syncthreads();
    }
    if (tid == 0) g_part[(b*32 + blockIdx.x)*2 + 1] = red[0];
}

// ============================================================================
// K5a: reduce 32 tile partials per batch -> mu, rstd
// ============================================================================
__global__ void k_stats() {
    const int b = blockIdx.x, t = threadIdx.x;  // 32 threads
    float s  = g_part[(b*32 + t)*2];
    float ss = g_part[(b*32 + t)*2 + 1];
    #pragma unroll
    for (int o = 16; o > 0; o >>= 1) {
        s  += __shfl_down_sync(0xffffffffu, s,  o);
        ss += __shfl_down_sync(0xffffffffu, ss, o);
    }
    if (t == 0) {
        float mu  = s  * (1.0f/(float)NTOT);
        float var = ss * (1.0f/(float)NTOT) - mu*mu;
        g_stats[b*2]     = mu;
        g_stats[b*2 + 1] = rsqrtf(var + EPS);
    }
}

// ============================================================================
// K5b: in-place normalize d_out: (y-mu)*rstd*gamma[c] + beta[c]
// ============================================================================
__global__ __launch_bounds__(256) void k_norm(float* __restrict__ out,
                                              const float* __restrict__ gamma,
                                              const float* __restrict__ beta) {
    size_t f = (size_t)blockIdx.x*256 + threadIdx.x;   // float4 index
    size_t e = f*4;
    int b  = (int)(e >> 19);          // 524288 per batch
    int ch = (int)((e >> 12) & 127);  // 4096 per channel row
    float mu = g_stats[b*2], rs = g_stats[b*2+1];
    float g  = gamma[ch] * rs;
    float be = fmaf(-mu, g, beta[ch]);
    float4 y = ((float4*)out)[f];
    y.x = fmaf(y.x, g, be);
    y.y = fmaf(y.y, g, be);
    y.z = fmaf(y.z, g, be);
    y.w = fmaf(y.w, g, be);
    ((float4*)out)[f] = y;
}

// ============================================================================
extern "C" void kernel_launch(void* const* d_in, const int* in_sizes, int n_in,
                              void* d_out, int out_size) {
    const float* x     = (const float*)d_in[0];
    const float* Wqkv  = (const float*)d_in[1];
    const float* Wout  = (const float*)d_in[2];
    const float* bout  = (const float*)d_in[3];
    const float* gamma = (const float*)d_in[4];
    const float* beta  = (const float*)d_in[5];
    float* out = (float*)d_out;

    const int smem_k1 = (128*128 + 128*WT_STRIDE + 96*128) * 4;  // 164352 B
    const int smem_k4 = (128*128 + 128*128) * 4;                 // 131072 B
    cudaFuncSetAttribute(k_qkv, cudaFuncAttributeMaxDynamicSharedMemorySize, smem_k1);
    cudaFuncSetAttribute(k_y,   cudaFuncAttributeMaxDynamicSharedMemorySize, smem_k4);

    k_qkv  <<<dim3(32, NB), 256, smem_k1>>>(x, Wqkv);
    k_kstats<<<NB*HID, 256>>>();
    k_ctx  <<<dim3(NHD, NB), 256>>>();
    k_m    <<<NB, 256>>>(Wout);
    k_y    <<<dim3(32, NB), 256, smem_k4>>>(bout, out);
    k_stats<<<NB, 32>>>();
    k_norm <<<(NB*NTOT)/(256*4), 256>>>(out, gamma, beta);
}

// round 5
// speedup vs baseline: 1.4957x; 1.4957x over previous
#include <cuda_runtime.h>
#include <math.h>

#define NB   32
#define NC   128
#define NPOS 4096
#define NHD  4
#define DH   32
#define HID  128
#define NTOT (NC*NPOS)            /* 524288 per-batch elements */
#define SCALE 0.17677669529663687f
#define EPS   1e-5f
#define NSL  4                    /* n-slices for k_ctx */

// ---------------- device scratch (static: no allocs allowed) ----------------
__device__ float g_q[NB*HID*NPOS];        // softmaxed(q)*scale, [b][h*32+d][n]
__device__ float g_k[NB*HID*NPOS];        // raw k
__device__ float g_v[NB*HID*NPOS];        // raw v
__device__ float g_kstats[NB*HID*2];      // per (b,hd): rowmax, rowsumexp
__device__ float g_ctxp[NSL*NB*NHD*DH*DH];// sliced partial ctx
__device__ float g_M[NB*HID*NC];          // [b][hd][o]
__device__ float g_part[NB*32*2];         // per (b, ntile): sum, sumsq
__device__ float g_stats[NB*2];           // per b: mu, rstd

// ============================================================================
// K1: QKV GEMM (per batch: 384 x 4096 x 128) + q-softmax over d, fused.
// ============================================================================
#define WT_STRIDE 97   /* 97 % 32 == 1 -> conflict-free loads AND stores */

__global__ __launch_bounds__(256) void k_qkv(const float* __restrict__ x,
                                             const float* __restrict__ Wqkv) {
    extern __shared__ float sm[];
    float* xt = sm;                          // [128][128] (c, n)
    float* wt = sm + 128*128;                // [kk][lr] stride WT_STRIDE
    float* st = wt + 128*WT_STRIDE;          // [96][128] stage (q,k,v rows)
    float4* xt4 = (float4*)xt;
    float4* st4 = (float4*)st;

    const int b   = blockIdx.y;
    const int n0  = blockIdx.x * 128;
    const int tid = threadIdx.x;
    const int ty  = tid >> 4, tx = tid & 15;
    const int r0  = ty * 6;

    const float4* xg = (const float4*)(x + (size_t)b*NTOT + n0);
    for (int i = tid; i < 128*32; i += 256) {
        int r = i >> 5, c4 = i & 31;
        xt4[i] = xg[(size_t)r*(NPOS/4) + c4];
    }
    __syncthreads();

    for (int h = 0; h < NHD; h++) {
        for (int i = tid; i < 96*128; i += 256) {
            int kk = i & 127, lr = i >> 7;
            int s = lr >> 5, d = lr & 31;
            wt[kk*WT_STRIDE + lr] = Wqkv[(size_t)(s*128 + h*32 + d)*128 + kk];
        }
        __syncthreads();

        float acc[6][8];
        #pragma unroll
        for (int j = 0; j < 6; j++)
            #pragma unroll
            for (int i2 = 0; i2 < 8; i2++) acc[j][i2] = 0.f;

        for (int kk = 0; kk < 128; kk++) {
            float4 xa = xt4[kk*32 + tx*2];
            float4 xb = xt4[kk*32 + tx*2 + 1];
            float xv[8] = {xa.x,xa.y,xa.z,xa.w, xb.x,xb.y,xb.z,xb.w};
            #pragma unroll
            for (int j = 0; j < 6; j++) {
                float w = wt[kk*WT_STRIDE + r0 + j];
                #pragma unroll
                for (int i2 = 0; i2 < 8; i2++)
                    acc[j][i2] = fmaf(w, xv[i2], acc[j][i2]);
            }
        }

        #pragma unroll
        for (int j = 0; j < 6; j++) {
            st4[(r0+j)*32 + tx*2]     = make_float4(acc[j][0],acc[j][1],acc[j][2],acc[j][3]);
            st4[(r0+j)*32 + tx*2 + 1] = make_float4(acc[j][4],acc[j][5],acc[j][6],acc[j][7]);
        }
        __syncthreads();

        // q softmax over d (rows 0..31) per column, times SCALE
        if (tid < 128) {
            float m = st[tid];
            #pragma unroll 8
            for (int d = 1; d < 32; d++) m = fmaxf(m, st[d*128 + tid]);
            float ssum = 0.f;
            #pragma unroll 8
            for (int d = 0; d < 32; d++) {
                float e = __expf(st[d*128 + tid] - m);
                st[d*128 + tid] = e;
                ssum += e;
            }
            float invs = SCALE / ssum;
            #pragma unroll 8
            for (int d = 0; d < 32; d++) st[d*128 + tid] *= invs;
        }
        __syncthreads();

        size_t obase = (size_t)b*HID*NPOS + (size_t)(h*32)*NPOS + n0;
        for (int i = tid; i < 96*32; i += 256) {
            int r = i >> 5, c4 = i & 31;
            float* dst = (r < 32) ? g_q : (r < 64 ? g_k : g_v);
            ((float4*)(dst + obase + (size_t)(r & 31)*NPOS))[c4] = st4[i];
        }
        __syncthreads();
    }
}

// ============================================================================
// K2: per (b,hd)-row of k: max and sum(exp) over n=4096
// ============================================================================
__global__ __launch_bounds__(256) void k_kstats() {
    __shared__ float red[256];
    const int row = blockIdx.x;
    const int tid = threadIdx.x;
    const float* kr = g_k + (size_t)row * NPOS;

    float m = -1e30f;
    for (int i = tid; i < NPOS; i += 256) m = fmaxf(m, kr[i]);
    red[tid] = m; __syncthreads();
    for (int s2 = 128; s2 > 0; s2 >>= 1) {
        if (tid < s2) red[tid] = fmaxf(red[tid], red[tid+s2]);
        __syncthreads();
    }
    m = red[0]; __syncthreads();

    float ssum = 0.f;
    for (int i = tid; i < NPOS; i += 256) ssum += __expf(kr[i] - m);
    red[tid] = ssum; __syncthreads();
    for (int s2 = 128; s2 > 0; s2 >>= 1) {
        if (tid < s2) red[tid] += red[tid+s2];
        __syncthreads();
    }
    if (tid == 0) { g_kstats[row*2] = m; g_kstats[row*2+1] = red[0]; }
}

// ============================================================================
// K3: partial context over an n-slice of 1024.
// ctxp[sl][b,h,d,e] = sum_{n in slice} softmax_k[d,n] * v[e,n]
// ============================================================================
#define CH 64
__global__ __launch_bounds__(256) void k_ctx() {
    __shared__ float ks[32*CH];        // raw k chunk [d][n]
    __shared__ float kst[CH*33];       // transformed, transposed [n][d] (pad 33)
    __shared__ float vs[32*CH];        // v chunk [e][n]
    __shared__ float mx[32], inv[32];

    const int tid = threadIdx.x;
    const int h = blockIdx.x, b = blockIdx.y, sl = blockIdx.z;
    if (tid < 32) {
        int row = b*HID + h*32 + tid;
        mx[tid]  = g_kstats[row*2];
        inv[tid] = 1.0f / g_kstats[row*2 + 1];
    }
    const int d  = tid & 31;
    const int eg = tid >> 5;          // 8 groups of 4 e-values
    float a0=0.f, a1=0.f, a2=0.f, a3=0.f;
    const size_t base = (size_t)(b*HID + h*32) * NPOS;
    const int nbeg = sl * (NPOS/NSL), nend = nbeg + (NPOS/NSL);

    for (int n0 = nbeg; n0 < nend; n0 += CH) {
        __syncthreads();
        for (int i = tid; i < 32*(CH/4); i += 256) {
            int r = i >> 4, c4 = i & 15;
            ((float4*)ks)[i] = *(const float4*)(g_k + base + (size_t)r*NPOS + n0 + c4*4);
            ((float4*)vs)[i] = *(const float4*)(g_v + base + (size_t)r*NPOS + n0 + c4*4);
        }
        __syncthreads();
        for (int i = tid; i < 32*CH; i += 256) {
            int r = i >> 6, c = i & (CH-1);
            kst[c*33 + r] = __expf(ks[i] - mx[r]) * inv[r];
        }
        __syncthreads();
        const float* v0 = vs + (eg*4 + 0)*CH;
        const float* v1 = vs + (eg*4 + 1)*CH;
        const float* v2 = vs + (eg*4 + 2)*CH;
        const float* v3 = vs + (eg*4 + 3)*CH;
        #pragma unroll 8
        for (int nn = 0; nn < CH; nn++) {
            float kv = kst[nn*33 + d];
            a0 = fmaf(kv, v0[nn], a0);
            a1 = fmaf(kv, v1[nn], a1);
            a2 = fmaf(kv, v2[nn], a2);
            a3 = fmaf(kv, v3[nn], a3);
        }
    }
    float* cp = g_ctxp + (((size_t)sl*NB + b)*NHD + h)*DH*DH + d*DH + eg*4;
    cp[0]=a0; cp[1]=a1; cp[2]=a2; cp[3]=a3;
}

// ============================================================================
// K4a: reduce ctx slices; M[b][hd][o] = sum_e W_out[o][h*32+e] * ctx[b][h][d][e]
// smem-staged, conflict-free.  grid = NB.
// ============================================================================
__global__ __launch_bounds__(256) void k_m(const float* __restrict__ Wout) {
    extern __shared__ float sm[];
    float* wts = sm;                  // [o][c] stride 129: 128*129 floats
    float* csm = sm + 128*129;        // ctx [hd][e]: 4096 floats
    const int b = blockIdx.x, tid = threadIdx.x;

    for (int i = tid; i < 128*128; i += 256) {
        int o = i >> 7, c = i & 127;
        wts[o*129 + c] = Wout[i];
    }
    for (int i = tid; i < NHD*DH*DH; i += 256) {
        size_t off = (size_t)b*NHD*DH*DH + i;
        float s = g_ctxp[off];
        #pragma unroll
        for (int sl2 = 1; sl2 < NSL; sl2++)
            s += g_ctxp[(size_t)sl2*NB*NHD*DH*DH + off];
        csm[i] = s;
    }
    __syncthreads();

    #pragma unroll 4
    for (int j = 0; j < 64; j++) {
        int m  = j*256 + tid;          // m = hd*128 + o
        int hd = m >> 7, o = m & 127;
        int hh = hd >> 5;
        const float* wr = wts + o*129 + hh*32;
        const float* cr = csm + hd*32;
        float s = 0.f;
        #pragma unroll
        for (int e = 0; e < 32; e++) s = fmaf(wr[e], cr[e], s);
        g_M[(size_t)b*HID*NC + m] = s;
    }
}

// ============================================================================
// K4b: y[b][o][n] = sum_hd M[b][hd][o]*q[b][hd][n] + b_out[o]; + GN partials
// ============================================================================
__global__ __launch_bounds__(256) void k_y(const float* __restrict__ bout,
                                           float* __restrict__ out) {
    extern __shared__ float sm[];
    float* qt = sm;              // [hd][128]
    float* mt = sm + 128*128;    // [hd][o]
    __shared__ float red[256];

    const int b = blockIdx.y, n0 = blockIdx.x*128, tid = threadIdx.x;
    const int ty = tid >> 4, tx = tid & 15;

    const float4* qg = (const float4*)(g_q + (size_t)b*HID*NPOS + n0);
    for (int i = tid; i < 128*32; i += 256) {
        int r = i >> 5, c4 = i & 31;
        ((float4*)qt)[i] = qg[(size_t)r*(NPOS/4) + c4];
    }
    const float4* mg = (const float4*)(g_M + (size_t)b*HID*NC);
    for (int i = tid; i < 128*32; i += 256) ((float4*)mt)[i] = mg[i];
    __syncthreads();

    float acc[8][8];
    #pragma unroll
    for (int j = 0; j < 8; j++)
        #pragma unroll
        for (int i2 = 0; i2 < 8; i2++) acc[j][i2] = 0.f;

    for (int kk = 0; kk < 128; kk++) {
        float4 ma = ((float4*)mt)[kk*32 + ty*2];
        float4 mb = ((float4*)mt)[kk*32 + ty*2 + 1];
        float4 qa = ((float4*)qt)[kk*32 + tx*2];
        float4 qb = ((float4*)qt)[kk*32 + tx*2 + 1];
        float av[8] = {ma.x,ma.y,ma.z,ma.w, mb.x,mb.y,mb.z,mb.w};
        float bv[8] = {qa.x,qa.y,qa.z,qa.w, qb.x,qb.y,qb.z,qb.w};
        #pragma unroll
        for (int j = 0; j < 8; j++)
            #pragma unroll
            for (int i2 = 0; i2 < 8; i2++)
                acc[j][i2] = fmaf(av[j], bv[i2], acc[j][i2]);
    }

    float lsum = 0.f, lsq = 0.f;
    #pragma unroll
    for (int j = 0; j < 8; j++) {
        int o = ty*8 + j;
        float bias = bout[o];
        #pragma unroll
        for (int i2 = 0; i2 < 8; i2++) {
            float v = acc[j][i2] + bias;
            acc[j][i2] = v;
            lsum += v;
            lsq  = fmaf(v, v, lsq);
        }
        float4* orow = (float4*)(out + (size_t)b*NTOT + (size_t)o*NPOS + n0);
        orow[tx*2]     = make_float4(acc[j][0],acc[j][1],acc[j][2],acc[j][3]);
        orow[tx*2 + 1] = make_float4(acc[j][4],acc[j][5],acc[j][6],acc[j][7]);
    }

    red[tid] = lsum; __syncthreads();
    for (int s2 = 128; s2 > 0; s2 >>= 1) {
        if (tid < s2) red[tid] += red[tid+s2];
        __syncthreads();
    }
    if (tid == 0) g_part[(b*32 + blockIdx.x)*2] = red[0];
    __syncthreads();
    red[tid] = lsq; __syncthreads();
    for (int s2 = 128; s2 > 0; s2 >>= 1) {
        if (tid < s2) red[tid] += red[tid+s2];
        __syncthreads();
    }
    if (tid == 0) g_part[(b*32 + blockIdx.x)*2 + 1] = red[0];
}

// ============================================================================
// K5a: reduce 32 tile partials per batch -> mu, rstd
// ============================================================================
__global__ void k_stats() {
    const int b = blockIdx.x, t = threadIdx.x;  // 32 threads
    float s  = g_part[(b*32 + t)*2];
    float ss = g_part[(b*32 + t)*2 + 1];
    #pragma unroll
    for (int o = 16; o > 0; o >>= 1) {
        s  += __shfl_down_sync(0xffffffffu, s,  o);
        ss += __shfl_down_sync(0xffffffffu, ss, o);
    }
    if (t == 0) {
        float mu  = s  * (1.0f/(float)NTOT);
        float var = ss * (1.0f/(float)NTOT) - mu*mu;
        g_stats[b*2]     = mu;
        g_stats[b*2 + 1] = rsqrtf(var + EPS);
    }
}

// ============================================================================
// K5b: in-place normalize d_out
// ============================================================================
__global__ __launch_bounds__(256) void k_norm(float* __restrict__ out,
                                              const float* __restrict__ gamma,
                                              const float* __restrict__ beta) {
    size_t f = (size_t)blockIdx.x*256 + threadIdx.x;   // float4 index
    size_t e = f*4;
    int b  = (int)(e >> 19);          // 524288 per batch
    int ch = (int)((e >> 12) & 127);  // 4096 per channel row
    float mu = g_stats[b*2], rs = g_stats[b*2+1];
    float g  = gamma[ch] * rs;
    float be = fmaf(-mu, g, beta[ch]);
    float4 y = ((float4*)out)[f];
    y.x = fmaf(y.x, g, be);
    y.y = fmaf(y.y, g, be);
    y.z = fmaf(y.z, g, be);
    y.w = fmaf(y.w, g, be);
    ((float4*)out)[f] = y;
}

// ============================================================================
extern "C" void kernel_launch(void* const* d_in, const int* in_sizes, int n_in,
                              void* d_out, int out_size) {
    const float* x     = (const float*)d_in[0];
    const float* Wqkv  = (const float*)d_in[1];
    const float* Wout  = (const float*)d_in[2];
    const float* bout  = (const float*)d_in[3];
    const float* gamma = (const float*)d_in[4];
    const float* beta  = (const float*)d_in[5];
    float* out = (float*)d_out;

    const int smem_k1 = (128*128 + 128*WT_STRIDE + 96*128) * 4;  // 164352 B
    const int smem_k4 = (128*128 + 128*128) * 4;                 // 131072 B
    const int smem_km = (128*129 + NHD*DH*DH) * 4;               // 82432 B
    cudaFuncSetAttribute(k_qkv, cudaFuncAttributeMaxDynamicSharedMemorySize, smem_k1);
    cudaFuncSetAttribute(k_y,   cudaFuncAttributeMaxDynamicSharedMemorySize, smem_k4);
    cudaFuncSetAttribute(k_m,   cudaFuncAttributeMaxDynamicSharedMemorySize, smem_km);

    k_qkv  <<<dim3(32, NB), 256, smem_k1>>>(x, Wqkv);
    k_kstats<<<NB*HID, 256>>>();
    k_ctx  <<<dim3(NHD, NB, NSL), 256>>>();
    k_m    <<<NB, 256, smem_km>>>(Wout);
    k_y    <<<dim3(32, NB), 256, smem_k4>>>(bout, out);
    k_stats<<<NB, 32>>>();
    k_norm <<<(NB*NTOT)/(256*4), 256>>>(out, gamma, beta);
}

// round 6
// speedup vs baseline: 1.5584x; 1.0419x over previous
#include <cuda_runtime.h>
#include <mma.h>
#include <math.h>

using namespace nvcuda;

#define NB   32
#define NC   128
#define NPOS 4096
#define NHD  4
#define DH   32
#define HID  128
#define NTOT (NC*NPOS)
#define SCALE 0.17677669529663687f
#define EPS   1e-5f
#define NSL  4

// ---------------- device scratch ----------------
__device__ float g_q[NB*HID*NPOS];        // softmaxed(q)*scale, [b][hd][n]
__device__ float g_k[NB*HID*NPOS];        // raw k [b][hd][n]
__device__ float g_v[NB*HID*NPOS];        // raw v [b][hd][n]
__device__ float g_kstats[NB*HID*2];
__device__ float g_ctxp[NSL*NB*NHD*DH*DH];
__device__ float g_M[NB*NC*HID];          // TRANSPOSED: [b][o][hd]
__device__ float g_part[NB*32*2];
__device__ float g_stats[NB*2];

// ============================================================================
// K1: QKV GEMM via WMMA tf32.  C[384][64] = W[384][128] x X[128][64-tile]
// Rows 0-127 = q (fused d-softmax), 128-255 = k, 256-383 = v.
// block: 384 thr (12 warps).  grid: (NPOS/64, NB).
// ============================================================================
#define K1_LDW 40    /* W chunk ld: 32 + 8 pad */
#define K1_LDX 72    /* X chunk ld: 64 + 8 pad */
#define K1_NT  64    /* n-tile */
// smem floats: Ws 384*40=15360 | Xs 32*72=2304 | Qs 128*72=9216
#define K1_WS_OFF 0
#define K1_XS_OFF 15360
#define K1_QS_OFF 17664
#define K1_SMEM   ((17664 + 9216) * 4)

__global__ __launch_bounds__(384) void k_qkv(const float* __restrict__ x,
                                             const float* __restrict__ Wqkv) {
    extern __shared__ float sm[];
    float* Ws = sm + K1_WS_OFF;
    float* Xs = sm + K1_XS_OFF;
    float* Qs = sm + K1_QS_OFF;

    const int b   = blockIdx.y;
    const int n0  = blockIdx.x * K1_NT;
    const int tid = threadIdx.x;
    const int wid = tid >> 5;

    wmma::fragment<wmma::accumulator, 16, 16, 8, float> acc[2][4];
    #pragma unroll
    for (int r = 0; r < 2; r++)
        #pragma unroll
        for (int c = 0; c < 4; c++) wmma::fill_fragment(acc[r][c], 0.f);

    const int fr0 = wid * 2;             // frag rows fr0, fr0+1 (rows 32*wid..+31)

    for (int kc = 0; kc < 4; kc++) {
        __syncthreads();
        // W chunk [384][32] -> Ws, tf32. coalesced: 32 consecutive kk per row
        for (int i = tid; i < 384*32; i += 384) {
            int o = i >> 5, kk = i & 31;
            Ws[o*K1_LDW + kk] = wmma::__float_to_tf32(Wqkv[(size_t)o*128 + kc*32 + kk]);
        }
        // X chunk [32][64] -> Xs, tf32
        const float* xb = x + (size_t)b*NTOT + (size_t)(kc*32)*NPOS + n0;
        for (int i = tid; i < 32*K1_NT; i += 384) {
            int kk = i >> 6, n = i & 63;
            Xs[kk*K1_LDX + n] = wmma::__float_to_tf32(xb[(size_t)kk*NPOS + n]);
        }
        __syncthreads();

        #pragma unroll
        for (int s = 0; s < 4; s++) {
            wmma::fragment<wmma::matrix_a, 16, 16, 8, wmma::precision::tf32, wmma::row_major> a0, a1;
            wmma::load_matrix_sync(a0, Ws + (fr0    )*16*K1_LDW + s*8, K1_LDW);
            wmma::load_matrix_sync(a1, Ws + (fr0 + 1)*16*K1_LDW + s*8, K1_LDW);
            #pragma unroll
            for (int cf = 0; cf < 4; cf++) {
                wmma::fragment<wmma::matrix_b, 16, 16, 8, wmma::precision::tf32, wmma::row_major> bf;
                wmma::load_matrix_sync(bf, Xs + (s*8)*K1_LDX + cf*16, K1_LDX);
                wmma::mma_sync(acc[0][cf], a0, bf, acc[0][cf]);
                wmma::mma_sync(acc[1][cf], a1, bf, acc[1][cf]);
            }
        }
    }

    // store: q rows -> Qs stage; k/v rows -> global directly
    #pragma unroll
    for (int r = 0; r < 2; r++) {
        int row0 = (fr0 + r) * 16;
        #pragma unroll
        for (int cf = 0; cf < 4; cf++) {
            if (row0 < 128) {
                wmma::store_matrix_sync(Qs + row0*K1_LDX + cf*16, acc[r][cf], K1_LDX, wmma::mem_row_major);
            } else if (row0 < 256) {
                wmma::store_matrix_sync(g_k + ((size_t)b*HID + row0-128)*NPOS + n0 + cf*16,
                                        acc[r][cf], NPOS, wmma::mem_row_major);
            } else {
                wmma::store_matrix_sync(g_v + ((size_t)b*HID + row0-256)*NPOS + n0 + cf*16,
                                        acc[r][cf], NPOS, wmma::mem_row_major);
            }
        }
    }
    __syncthreads();

    // q softmax over d within each head, per column; *SCALE
    if (tid < NHD*K1_NT) {
        int h = tid >> 6, n = tid & 63;
        float* qc = Qs + (h*32)*K1_LDX + n;
        float m = qc[0];
        #pragma unroll 8
        for (int d = 1; d < 32; d++) m = fmaxf(m, qc[d*K1_LDX]);
        float ssum = 0.f;
        #pragma unroll 8
        for (int d = 0; d < 32; d++) {
            float e = __expf(qc[d*K1_LDX] - m);
            qc[d*K1_LDX] = e;
            ssum += e;
        }
        float invs = SCALE / ssum;
        #pragma unroll 8
        for (int d = 0; d < 32; d++) qc[d*K1_LDX] *= invs;
    }
    __syncthreads();

    // write q rows
    float4* Qs4 = (float4*)Qs;
    for (int i = tid; i < 128*(K1_NT/4); i += 384) {
        int r = i >> 4, c4 = i & 15;
        ((float4*)(g_q + ((size_t)b*HID + r)*NPOS + n0))[c4] = Qs4[r*(K1_LDX/4) + c4];
    }
}

// ============================================================================
// K2: per (b,hd)-row of k: max and sum(exp) over n=4096
// ============================================================================
__global__ __launch_bounds__(256) void k_kstats() {
    __shared__ float red[256];
    const int row = blockIdx.x;
    const int tid = threadIdx.x;
    const float* kr = g_k + (size_t)row * NPOS;

    float m = -1e30f;
    for (int i = tid; i < NPOS; i += 256) m = fmaxf(m, kr[i]);
    red[tid] = m; __syncthreads();
    for (int s2 = 128; s2 > 0; s2 >>= 1) {
        if (tid < s2) red[tid] = fmaxf(red[tid], red[tid+s2]);
        __syncthreads();
    }
    m = red[0]; __syncthreads();

    float ssum = 0.f;
    for (int i = tid; i < NPOS; i += 256) ssum += __expf(kr[i] - m);
    red[tid] = ssum; __syncthreads();
    for (int s2 = 128; s2 > 0; s2 >>= 1) {
        if (tid < s2) red[tid] += red[tid+s2];
        __syncthreads();
    }
    if (tid == 0) { g_kstats[row*2] = m; g_kstats[row*2+1] = red[0]; }
}

// ============================================================================
// K3: partial context over an n-slice of 1024.
// ============================================================================
#define CH 64
__global__ __launch_bounds__(256) void k_ctx() {
    __shared__ float ks[32*CH];
    __shared__ float kst[CH*33];
    __shared__ float vs[32*CH];
    __shared__ float mx[32], inv[32];

    const int tid = threadIdx.x;
    const int h = blockIdx.x, b = blockIdx.y, sl = blockIdx.z;
    if (tid < 32) {
        int row = b*HID + h*32 + tid;
        mx[tid]  = g_kstats[row*2];
        inv[tid] = 1.0f / g_kstats[row*2 + 1];
    }
    const int d  = tid & 31;
    const int eg = tid >> 5;
    float a0=0.f, a1=0.f, a2=0.f, a3=0.f;
    const size_t base = (size_t)(b*HID + h*32) * NPOS;
    const int nbeg = sl * (NPOS/NSL), nend = nbeg + (NPOS/NSL);

    for (int n0 = nbeg; n0 < nend; n0 += CH) {
        __syncthreads();
        for (int i = tid; i < 32*(CH/4); i += 256) {
            int r = i >> 4, c4 = i & 15;
            ((float4*)ks)[i] = *(const float4*)(g_k + base + (size_t)r*NPOS + n0 + c4*4);
            ((float4*)vs)[i] = *(const float4*)(g_v + base + (size_t)r*NPOS + n0 + c4*4);
        }
        __syncthreads();
        for (int i = tid; i < 32*CH; i += 256) {
            int r = i >> 6, c = i & (CH-1);
            kst[c*33 + r] = __expf(ks[i] - mx[r]) * inv[r];
        }
        __syncthreads();
        const float* v0 = vs + (eg*4 + 0)*CH;
        const float* v1 = vs + (eg*4 + 1)*CH;
        const float* v2 = vs + (eg*4 + 2)*CH;
        const float* v3 = vs + (eg*4 + 3)*CH;
        #pragma unroll 8
        for (int nn = 0; nn < CH; nn++) {
            float kv = kst[nn*33 + d];
            a0 = fmaf(kv, v0[nn], a0);
            a1 = fmaf(kv, v1[nn], a1);
            a2 = fmaf(kv, v2[nn], a2);
            a3 = fmaf(kv, v3[nn], a3);
        }
    }
    float* cp = g_ctxp + (((size_t)sl*NB + b)*NHD + h)*DH*DH + d*DH + eg*4;
    cp[0]=a0; cp[1]=a1; cp[2]=a2; cp[3]=a3;
}

// ============================================================================
// K4a: reduce ctx slices; M[b][o][hd] = sum_e W_out[o][h*32+e]*ctx[b][h][d][e]
// grid (NB, 4): blockIdx.y = o-quarter.  Writes TRANSPOSED g_M.
// ============================================================================
__global__ __launch_bounds__(256) void k_m(const float* __restrict__ Wout) {
    extern __shared__ float sm[];
    float* wts = sm;                  // [32][129] this o-quarter
    float* csm = sm + 32*129;         // ctx [hd][e]: 4096 floats
    const int b = blockIdx.x, oq = blockIdx.y, tid = threadIdx.x;
    const int o0 = oq * 32;

    for (int i = tid; i < 32*128; i += 256) {
        int o = i >> 7, c = i & 127;
        wts[o*129 + c] = Wout[(size_t)(o0 + o)*128 + c];
    }
    for (int i = tid; i < NHD*DH*DH; i += 256) {
        size_t off = (size_t)b*NHD*DH*DH + i;
        float s = g_ctxp[off];
        #pragma unroll
        for (int sl2 = 1; sl2 < NSL; sl2++)
            s += g_ctxp[(size_t)sl2*NB*NHD*DH*DH + off];
        csm[i] = s;
    }
    __syncthreads();

    #pragma unroll 4
    for (int j = 0; j < 16; j++) {
        int m  = j*256 + tid;          // m = ol*128 + hd  (ol in quarter)
        int ol = m >> 7, hd = m & 127;
        int hh = hd >> 5;
        const float* wr = wts + ol*129 + hh*32;
        const float* cr = csm + hd*32;
        float s = 0.f;
        #pragma unroll
        for (int e = 0; e < 32; e++) s = fmaf(wr[e], cr[e], s);
        g_M[((size_t)b*NC + o0 + ol)*HID + hd] = s;   // transposed [b][o][hd]
    }
}

// ============================================================================
// K4b: y[b][o][n] = sum_hd M[b][o][hd]*q[b][hd][n] + b_out[o] via WMMA tf32.
// block 256 thr (8 warps), tile 128x128, K=128.  grid (32, NB).
// ============================================================================
#define K4_LD 136
#define K4_MS_OFF 0
#define K4_QT_OFF (128*K4_LD)          /* Qt; reused as stage after MMA */
#define K4_SMEM   ((128*K4_LD*2) * 4)  /* 139264 B */

__global__ __launch_bounds__(256) void k_y(const float* __restrict__ bout,
                                           float* __restrict__ out) {
    extern __shared__ float sm[];
    float* Ms = sm + K4_MS_OFF;        // A: [o][hd] tf32
    float* Qt = sm + K4_QT_OFF;        // B: [hd][n] tf32; later stage
    __shared__ float red[256];

    const int b = blockIdx.y, n0 = blockIdx.x*128, tid = threadIdx.x;
    const int wid = tid >> 5;

    const float* mg = g_M + (size_t)b*NC*HID;
    for (int i = tid; i < 128*128; i += 256) {
        int o = i >> 7, hd = i & 127;
        Ms[o*K4_LD + hd] = wmma::__float_to_tf32(mg[i]);
    }
    const float* qg = g_q + (size_t)b*HID*NPOS + n0;
    for (int i = tid; i < 128*128; i += 256) {
        int hd = i >> 7, n = i & 127;
        Qt[hd*K4_LD + n] = wmma::__float_to_tf32(qg[(size_t)hd*NPOS + n]);
    }
    __syncthreads();

    wmma::fragment<wmma::accumulator, 16, 16, 8, float> acc[8];
    #pragma unroll
    for (int c = 0; c < 8; c++) wmma::fill_fragment(acc[c], 0.f);

    const int row0 = wid * 16;
    #pragma unroll
    for (int s = 0; s < 16; s++) {
        wmma::fragment<wmma::matrix_a, 16, 16, 8, wmma::precision::tf32, wmma::row_major> a;
        wmma::load_matrix_sync(a, Ms + row0*K4_LD + s*8, K4_LD);
        #pragma unroll
        for (int cf = 0; cf < 8; cf++) {
            wmma::fragment<wmma::matrix_b, 16, 16, 8, wmma::precision::tf32, wmma::row_major> bf;
            wmma::load_matrix_sync(bf, Qt + (s*8)*K4_LD + cf*16, K4_LD);
            wmma::mma_sync(acc[cf], a, bf, acc[cf]);
        }
    }
    __syncthreads();               // all warps done reading Qt before reuse

    float* stage = Qt;
    #pragma unroll
    for (int cf = 0; cf < 8; cf++)
        wmma::store_matrix_sync(stage + row0*K4_LD + cf*16, acc[cf], K4_LD, wmma::mem_row_major);
    __syncthreads();

    // bias + GN partials + write
    float lsum = 0.f, lsq = 0.f;
    float4* st4 = (float4*)stage;
    for (int i = tid; i < 128*32; i += 256) {
        int r = i >> 5, c4 = i & 31;
        float bias = bout[r];
        float4 v = st4[r*(K4_LD/4) + c4];
        v.x += bias; v.y += bias; v.z += bias; v.w += bias;
        lsum += v.x + v.y + v.z + v.w;
        lsq  = fmaf(v.x,v.x, fmaf(v.y,v.y, fmaf(v.z,v.z, fmaf(v.w,v.w, lsq))));
        ((float4*)(out + (size_t)b*NTOT + (size_t)r*NPOS + n0))[c4] = v;
    }

    red[tid] = lsum; __syncthreads();
    for (int s2 = 128; s2 > 0; s2 >>= 1) {
        if (tid < s2) red[tid] += red[tid+s2];
        __syncthreads();
    }
    if (tid == 0) g_part[(b*32 + blockIdx.x)*2] = red[0];
    __syncthreads();
    red[tid] = lsq; __syncthreads();
    for (int s2 = 128; s2 > 0; s2 >>= 1) {
        if (tid < s2) red[tid] += red[tid+s2];
        __syncthreads();
    }
    if (tid == 0) g_part[(b*32 + blockIdx.x)*2 + 1] = red[0];
}

// ============================================================================
// K5a + K5b: GroupNorm stats and normalize
// ============================================================================
__global__ void k_stats() {
    const int b = blockIdx.x, t = threadIdx.x;
    float s  = g_part[(b*32 + t)*2];
    float ss = g_part[(b*32 + t)*2 + 1];
    #pragma unroll
    for (int o = 16; o > 0; o >>= 1) {
        s  += __shfl_down_sync(0xffffffffu, s,  o);
        ss += __shfl_down_sync(0xffffffffu, ss, o);
    }
    if (t == 0) {
        float mu  = s  * (1.0f/(float)NTOT);
        float var = ss * (1.0f/(float)NTOT) - mu*mu;
        g_stats[b*2]     = mu;
        g_stats[b*2 + 1] = rsqrtf(var + EPS);
    }
}

__global__ __launch_bounds__(256) void k_norm(float* __restrict__ out,
                                              const float* __restrict__ gamma,
                                              const float* __restrict__ beta) {
    size_t f = (size_t)blockIdx.x*256 + threadIdx.x;
    size_t e = f*4;
    int b  = (int)(e >> 19);
    int ch = (int)((e >> 12) & 127);
    float mu = g_stats[b*2], rs = g_stats[b*2+1];
    float g  = gamma[ch] * rs;
    float be = fmaf(-mu, g, beta[ch]);
    float4 y = ((float4*)out)[f];
    y.x = fmaf(y.x, g, be);
    y.y = fmaf(y.y, g, be);
    y.z = fmaf(y.z, g, be);
    y.w = fmaf(y.w, g, be);
    ((float4*)out)[f] = y;
}

// ============================================================================
extern "C" void kernel_launch(void* const* d_in, const int* in_sizes, int n_in,
                              void* d_out, int out_size) {
    const float* x     = (const float*)d_in[0];
    const float* Wqkv  = (const float*)d_in[1];
    const float* Wout  = (const float*)d_in[2];
    const float* bout  = (const float*)d_in[3];
    const float* gamma = (const float*)d_in[4];
    const float* beta  = (const float*)d_in[5];
    float* out = (float*)d_out;

    const int smem_km = (32*129 + NHD*DH*DH) * 4;   // 32896 B
    cudaFuncSetAttribute(k_qkv, cudaFuncAttributeMaxDynamicSharedMemorySize, K1_SMEM);
    cudaFuncSetAttribute(k_y,   cudaFuncAttributeMaxDynamicSharedMemorySize, K4_SMEM);
    cudaFuncSetAttribute(k_m,   cudaFuncAttributeMaxDynamicSharedMemorySize, smem_km);

    k_qkv  <<<dim3(NPOS/K1_NT, NB), 384, K1_SMEM>>>(x, Wqkv);
    k_kstats<<<NB*HID, 256>>>();
    k_ctx  <<<dim3(NHD, NB, NSL), 256>>>();
    k_m    <<<dim3(NB, 4), 256, smem_km>>>(Wout);
    k_y    <<<dim3(32, NB), 256, K4_SMEM>>>(bout, out);
    k_stats<<<NB, 32>>>();
    k_norm <<<(NB*NTOT)/(256*4), 256>>>(out, gamma, beta);
}